// round 1
// baseline (speedup 1.0000x reference)
#include <cuda_runtime.h>

// softmax(x, axis=-1) * v
// x: [B=4, H=16, S=1024, S=1024] fp32
// v: [B=4, H=16, 1, S=1024]      fp32  (broadcast over query dim)
// out: same shape as x.
//
// One CTA per softmax row. 256 threads * float4 = 1024 elements, fully
// register resident: x read once, out written once. v row (4 KB) is
// L2-resident (reused by 1024 CTAs per (b,h)).

#define THREADS 256
#define S_LEN 1024

__global__ __launch_bounds__(THREADS, 8)
void softmax_mul_kernel(const float* __restrict__ x,
                        const float* __restrict__ v,
                        float* __restrict__ out)
{
    const long long row = blockIdx.x;            // 0 .. B*H*S-1
    const int bh = (int)(row >> 10);             // row / S_LEN
    const long long xbase = row * S_LEN;
    const long long vbase = (long long)bh * S_LEN;

    const int tid = threadIdx.x;
    const int lane = tid & 31;
    const int wid  = tid >> 5;

    // Load 4 contiguous floats per thread.
    const float4 xv = reinterpret_cast<const float4*>(x + xbase)[tid];
    const float4 vv = reinterpret_cast<const float4*>(v + vbase)[tid];

    // ---- max reduce ----
    float m = fmaxf(fmaxf(xv.x, xv.y), fmaxf(xv.z, xv.w));
    #pragma unroll
    for (int off = 16; off > 0; off >>= 1)
        m = fmaxf(m, __shfl_xor_sync(0xFFFFFFFFu, m, off));

    __shared__ float smax[8];
    __shared__ float ssum[8];
    if (lane == 0) smax[wid] = m;
    __syncthreads();
    if (wid == 0) {
        float bm = smax[lane & 7];
        #pragma unroll
        for (int off = 4; off > 0; off >>= 1)
            bm = fmaxf(bm, __shfl_xor_sync(0xFFFFFFFFu, bm, off));
        if (lane == 0) smax[0] = bm;
    }
    __syncthreads();
    const float rowmax = smax[0];

    // ---- exp + sum reduce ----
    float4 e;
    e.x = __expf(xv.x - rowmax);
    e.y = __expf(xv.y - rowmax);
    e.z = __expf(xv.z - rowmax);
    e.w = __expf(xv.w - rowmax);

    float s = (e.x + e.y) + (e.z + e.w);
    #pragma unroll
    for (int off = 16; off > 0; off >>= 1)
        s += __shfl_xor_sync(0xFFFFFFFFu, s, off);
    if (lane == 0) ssum[wid] = s;
    __syncthreads();
    if (wid == 0) {
        float bs = ssum[lane & 7];
        #pragma unroll
        for (int off = 4; off > 0; off >>= 1)
            bs += __shfl_xor_sync(0xFFFFFFFFu, bs, off);
        if (lane == 0) ssum[0] = bs;
    }
    __syncthreads();
    const float inv = __frcp_rn(ssum[0]);

    // ---- scale by 1/sum and multiply by v, write out ----
    float4 o;
    o.x = e.x * inv * vv.x;
    o.y = e.y * inv * vv.y;
    o.z = e.z * inv * vv.z;
    o.w = e.w * inv * vv.w;

    reinterpret_cast<float4*>(out + xbase)[tid] = o;
}

extern "C" void kernel_launch(void* const* d_in, const int* in_sizes, int n_in,
                              void* d_out, int out_size)
{
    const float* x = (const float*)d_in[0];
    const float* v = (const float*)d_in[1];
    float* out = (float*)d_out;

    // rows = B*H*S = total_x / S_LEN
    const long long total = (long long)in_sizes[0];
    const int rows = (int)(total / S_LEN);   // 65536

    softmax_mul_kernel<<<rows, THREADS>>>(x, v, out);
}

// round 2
// speedup vs baseline: 1.0337x; 1.0337x over previous
#include <cuda_runtime.h>

// softmax(x, axis=-1) * v
// x: [4,16,1024,1024] fp32, v: [4,16,1,1024] fp32 (broadcast over queries).
//
// Warp-per-row: 32 lanes x 8 float4 = 1024 elems register-resident.
// MLP=8 LDG.128 per thread in the front batch; reductions are shuffle-only
// (no __syncthreads, no smem). v re-loaded in epilogue (L1/L2-resident).

#define THREADS 256
#define WARPS 8
#define S_LEN 1024
#define VEC 8   // float4 per lane

__global__ __launch_bounds__(THREADS)
void softmax_mul_kernel(const float* __restrict__ x,
                        const float* __restrict__ v,
                        float* __restrict__ out)
{
    const int lane = threadIdx.x & 31;
    const int wid  = threadIdx.x >> 5;
    const long long row = (long long)blockIdx.x * WARPS + wid;   // 0..65535
    const int bh = (int)(row >> 10);

    const float4* __restrict__ xr = reinterpret_cast<const float4*>(x + row * S_LEN);
    const float4* __restrict__ vr = reinterpret_cast<const float4*>(v + (long long)bh * S_LEN);
    float4* __restrict__ outr = reinterpret_cast<float4*>(out + row * S_LEN);

    // ---- front-batched row load: 8 independent LDG.128 per lane ----
    float4 e[VEC];
    #pragma unroll
    for (int i = 0; i < VEC; i++)
        e[i] = xr[lane + i * 32];

    // ---- max reduce (registers + warp shuffles only) ----
    float m = fmaxf(fmaxf(e[0].x, e[0].y), fmaxf(e[0].z, e[0].w));
    #pragma unroll
    for (int i = 1; i < VEC; i++) {
        m = fmaxf(m, fmaxf(e[i].x, e[i].y));
        m = fmaxf(m, fmaxf(e[i].z, e[i].w));
    }
    #pragma unroll
    for (int off = 16; off > 0; off >>= 1)
        m = fmaxf(m, __shfl_xor_sync(0xFFFFFFFFu, m, off));

    // ---- exp in place + sum reduce ----
    float s = 0.0f;
    #pragma unroll
    for (int i = 0; i < VEC; i++) {
        e[i].x = __expf(e[i].x - m);
        e[i].y = __expf(e[i].y - m);
        e[i].z = __expf(e[i].z - m);
        e[i].w = __expf(e[i].w - m);
        s += (e[i].x + e[i].y) + (e[i].z + e[i].w);
    }
    #pragma unroll
    for (int off = 16; off > 0; off >>= 1)
        s += __shfl_xor_sync(0xFFFFFFFFu, s, off);

    const float inv = __frcp_rn(s);

    // ---- epilogue: load v (cache-resident), scale, write ----
    #pragma unroll
    for (int i = 0; i < VEC; i++) {
        const float4 vv = vr[lane + i * 32];
        float4 o;
        o.x = e[i].x * inv * vv.x;
        o.y = e[i].y * inv * vv.y;
        o.z = e[i].z * inv * vv.z;
        o.w = e[i].w * inv * vv.w;
        outr[lane + i * 32] = o;
    }
}

extern "C" void kernel_launch(void* const* d_in, const int* in_sizes, int n_in,
                              void* d_out, int out_size)
{
    const float* x = (const float*)d_in[0];
    const float* v = (const float*)d_in[1];
    float* out = (float*)d_out;

    const long long total = (long long)in_sizes[0];
    const int rows = (int)(total / S_LEN);        // 65536
    const int blocks = rows / WARPS;              // 8192

    softmax_mul_kernel<<<blocks, THREADS>>>(x, v, out);
}